// round 3
// baseline (speedup 1.0000x reference)
#include <cuda_runtime.h>
#include <mma.h>
#include <cstdint>

using namespace nvcuda;

#define BATCH 8
#define CH    512
#define TT    8192
#define KS    7
#define TPAD  (TT + 6)
#define WN    (CH * CH * KS)   // 1835008

// ---------------- device scratch (no runtime allocation) ----------------
__device__ __align__(16) int8_t g_xT[(size_t)BATCH * TPAD * CH]; // [b][t+3][c] int8
__device__ __align__(16) int8_t g_wq[(size_t)KS * CH * CH];      // [tap][o][i] int8
__device__ float        g_rms[BATCH * TT];
__device__ unsigned int g_max_bits;
__device__ double       g_wsum;
__device__ float        g_qmul;   // 127 / act_scale
__device__ float        g_winv;   // 1 / w_scale
__device__ float        g_comb;   // act_scale/127 * w_scale

// ---------------- K0: reset scalars + zero halo rows of g_xT ----------------
__global__ void k_init() {
    int idx = blockIdx.x * blockDim.x + threadIdx.x;
    if (idx == 0) { g_max_bits = 0u; g_wsum = 0.0; }
    int total = BATCH * 6 * CH;
    if (idx < total) {
        int b = idx / (6 * CH);
        int r = (idx / CH) % 6;
        int c = idx % CH;
        int row = (r < 3) ? r : (TT + r);   // rows 0,1,2 and 8195,8196,8197
        g_xT[((size_t)b * TPAD + row) * CH + c] = 0;
    }
}

// ---------------- K1: sum |w| (double accumulation) ----------------
__global__ void k_wsum(const float* __restrict__ w, int n) {
    double s = 0.0;
    for (int i = blockIdx.x * blockDim.x + threadIdx.x; i < n;
         i += gridDim.x * blockDim.x)
        s += (double)fabsf(w[i]);
#pragma unroll
    for (int o = 16; o; o >>= 1) s += __shfl_xor_sync(0xffffffffu, s, o);
    if ((threadIdx.x & 31) == 0) atomicAdd(&g_wsum, s);
}

// ---------------- K2: per-(b,t) rms + global max|normalized| ----------------
// block: 256 threads, covers 32 t values of one batch; thread (tt, cg)
__global__ void k_stats(const float* __restrict__ x, const float* __restrict__ gamma) {
    int b  = blockIdx.y;
    int t0 = blockIdx.x * 32;
    int tt = threadIdx.x & 31;
    int cg = threadIdx.x >> 5;     // 0..7

    const float* xp = x + (size_t)b * CH * TT + t0 + tt;
    float ss = 0.f, mx = 0.f;
    for (int c = cg; c < CH; c += 8) {
        float v = xp[(size_t)c * TT];
        ss += v * v;
        mx = fmaxf(mx, fabsf(v * gamma[c]));
    }
    __shared__ float sss[8][33];
    __shared__ float smx[8][33];
    sss[cg][tt] = ss;
    smx[cg][tt] = mx;
    __syncthreads();
    if (cg == 0) {
        float S = 0.f, M = 0.f;
#pragma unroll
        for (int g = 0; g < 8; g++) { S += sss[g][tt]; M = fmaxf(M, smx[g][tt]); }
        float rms = 1.0f / sqrtf(S * (1.0f / (float)CH) + 1e-6f);
        g_rms[b * TT + t0 + tt] = rms;
        float cand = M * rms;
#pragma unroll
        for (int o = 16; o; o >>= 1)
            cand = fmaxf(cand, __shfl_xor_sync(0xffffffffu, cand, o));
        if (tt == 0) atomicMax(&g_max_bits, __float_as_uint(cand));
    }
}

// ---------------- K3: combine scalars ----------------
__global__ void k_combine() {
    float ma  = __uint_as_float(g_max_bits);
    float act = fmaxf(ma, 1e-5f);
    float ws  = fmaxf((float)(g_wsum / (double)WN), 1e-4f);
    g_qmul = 127.0f / act;
    g_winv = 1.0f / ws;
    g_comb = act * (1.0f / 127.0f) * ws;
}

// ---------------- K4: ternary weight quant -> g_wq[tap][o][i] ----------------
__global__ void k_wq(const float* __restrict__ w) {
    int idx = blockIdx.x * blockDim.x + threadIdx.x;
    if (idx >= WN) return;
    float winv = g_winv;
    float q = rintf(fminf(fmaxf(w[idx] * winv, -1.0f), 1.0f));
    int tap = idx % KS;
    int i   = (idx / KS) & (CH - 1);
    int o   = idx / (KS * CH);
    g_wq[(size_t)tap * (CH * CH) + (size_t)o * CH + i] = (int8_t)q;
}

// ---------------- K5: rmsnorm + 8-bit quant + transpose -> g_xT ----------------
// tile: 64 c x 64 t
__global__ void k_quant(const float* __restrict__ x, const float* __restrict__ gamma) {
    __shared__ int8_t s[64][68];
    int b  = blockIdx.z;
    int t0 = blockIdx.x * 64;
    int c0 = blockIdx.y * 64;
    int tt = threadIdx.x & 63;
    int cg = threadIdx.x >> 6;   // 0..3
    float qm = g_qmul;
    float rr = g_rms[b * TT + t0 + tt];
    const float* xb = x + (size_t)b * CH * TT + t0 + tt;
#pragma unroll
    for (int cc = cg; cc < 64; cc += 4) {
        int c = c0 + cc;
        float v = xb[(size_t)c * TT];
        float n = v * rr * gamma[c];
        float q = rintf(fminf(fmaxf(n * qm, -128.0f), 127.0f));
        s[cc][tt] = (int8_t)q;
    }
    __syncthreads();
    int co = threadIdx.x & 63;
    int tg = threadIdx.x >> 6;
#pragma unroll
    for (int tw = tg; tw < 64; tw += 4) {
        g_xT[((size_t)b * TPAD + t0 + tw + 3) * CH + c0 + co] = s[co][tw];
    }
}

// ---------------- K6: int8 tensor-core conv-GEMM ----------------
// CTA tile: 256 (t) x 128 (o), BK = 64 channels, 7 taps share one A halo tile.
#define MT  256
#define NT  128
#define BK  64
#define LDA 80
#define LDB 80

__global__ void __launch_bounds__(256, 1) k_conv(float* __restrict__ out) {
    __shared__ __align__(16) int8_t As[(MT + 8) * LDA];  // 264*80 = 21120 B
    __shared__ __align__(16) int8_t Bs[NT * LDB];        // 10240 B
    __shared__ __align__(16) int    epi[8 * 16 * 20];    // 10240 B (per-warp 16x20)

    int b  = blockIdx.z;
    int t0 = blockIdx.x * MT;
    int o0 = blockIdx.y * NT;
    int tid   = threadIdx.x;
    int warp  = tid >> 5;
    int lane  = tid & 31;
    int warpM = warp >> 1;   // 0..3  (64 t-rows each)
    int warpN = warp & 1;    // 0..1  (64 o-cols each)

    wmma::fragment<wmma::accumulator, 16, 16, 16, int> acc[4][4];
#pragma unroll
    for (int i = 0; i < 4; i++)
#pragma unroll
        for (int j = 0; j < 4; j++) wmma::fill_fragment(acc[i][j], 0);

    const int8_t* xbase = g_xT + ((size_t)b * TPAD + t0) * CH;

    for (int ci = 0; ci < CH; ci += BK) {
        __syncthreads();   // previous-iteration consumers of As/Bs done
        // Load A halo: (MT+6)=262 rows x 64 int8 (4 uint4 per row)
        for (int v = tid; v < (MT + 6) * 4; v += 256) {
            int row = v >> 2, seg = v & 3;
            uint4 d = *reinterpret_cast<const uint4*>(
                xbase + (size_t)row * CH + ci + seg * 16);
            *reinterpret_cast<uint4*>(As + row * LDA + seg * 16) = d;
        }
#pragma unroll 1
        for (int tap = 0; tap < KS; tap++) {
            if (tap) __syncthreads();   // prior-tap Bs reads complete
            const int8_t* wb = g_wq + (size_t)tap * (CH * CH) + (size_t)o0 * CH + ci;
            for (int v = tid; v < NT * 4; v += 256) {
                int row = v >> 2, seg = v & 3;
                uint4 d = *reinterpret_cast<const uint4*>(
                    wb + (size_t)row * CH + seg * 16);
                *reinterpret_cast<uint4*>(Bs + row * LDB + seg * 16) = d;
            }
            __syncthreads();            // As (first tap) + Bs ready
#pragma unroll
            for (int kk = 0; kk < BK; kk += 16) {
                wmma::fragment<wmma::matrix_a, 16, 16, 16, signed char,
                               wmma::row_major> af[4];
                wmma::fragment<wmma::matrix_b, 16, 16, 16, signed char,
                               wmma::col_major> bf[4];
#pragma unroll
                for (int mi = 0; mi < 4; mi++)
                    wmma::load_matrix_sync(
                        af[mi], As + (warpM * 64 + mi * 16 + tap) * LDA + kk, LDA);
#pragma unroll
                for (int ni = 0; ni < 4; ni++)
                    wmma::load_matrix_sync(
                        bf[ni], Bs + (warpN * 64 + ni * 16) * LDB + kk, LDB);
#pragma unroll
                for (int mi = 0; mi < 4; mi++)
#pragma unroll
                    for (int ni = 0; ni < 4; ni++)
                        wmma::mma_sync(acc[mi][ni], af[mi], bf[ni], acc[mi][ni]);
            }
        }
    }

    // Epilogue: C[t,o] -> out[b][o][t] * comb, via per-warp smem transpose
    float comb = g_comb;
    int* ep = epi + warp * 320;   // 16 x 20 ints
#pragma unroll 1
    for (int mi = 0; mi < 4; mi++) {
#pragma unroll 1
        for (int ni = 0; ni < 4; ni++) {
            wmma::store_matrix_sync(ep, acc[mi][ni], 20, wmma::mem_row_major);
            __syncwarp();
            int obase = o0 + warpN * 64 + ni * 16;
            int tbase = t0 + warpM * 64 + mi * 16;
            int r    = lane & 15;
            int tcol = (lane >> 4) * 8;
            float4 v, u;
            v.x = (float)ep[(tcol + 0) * 20 + r] * comb;
            v.y = (float)ep[(tcol + 1) * 20 + r] * comb;
            v.z = (float)ep[(tcol + 2) * 20 + r] * comb;
            v.w = (float)ep[(tcol + 3) * 20 + r] * comb;
            u.x = (float)ep[(tcol + 4) * 20 + r] * comb;
            u.y = (float)ep[(tcol + 5) * 20 + r] * comb;
            u.z = (float)ep[(tcol + 6) * 20 + r] * comb;
            u.w = (float)ep[(tcol + 7) * 20 + r] * comb;
            float* op = out + ((size_t)b * CH + obase + r) * (size_t)TT + tbase + tcol;
            *reinterpret_cast<float4*>(op)     = v;
            *reinterpret_cast<float4*>(op + 4) = u;
            __syncwarp();   // before next fragment reuses ep
        }
    }
}

// ---------------- launch ----------------
extern "C" void kernel_launch(void* const* d_in, const int* in_sizes, int n_in,
                              void* d_out, int out_size) {
    const float* x     = (const float*)d_in[0];   // (8, 512, 8192)
    const float* w     = (const float*)d_in[1];   // (512, 512, 7)
    const float* gamma = (const float*)d_in[2];   // (512,)
    float* out = (float*)d_out;                   // (8, 512, 8192)

    k_init<<<96, 256>>>();
    k_wsum<<<448, 256>>>(w, WN);
    k_stats<<<dim3(TT / 32, BATCH), 256>>>(x, gamma);
    k_combine<<<1, 1>>>();
    k_wq<<<(WN + 255) / 256, 256>>>(w);
    k_quant<<<dim3(TT / 64, CH / 64, BATCH), 256>>>(x, gamma);
    k_conv<<<dim3(TT / MT, CH / NT, BATCH), 256>>>(out);
}

// round 5
// speedup vs baseline: 2.4413x; 2.4413x over previous
#include <cuda_runtime.h>
#include <cstdint>

#define BATCH 8
#define CH    512
#define TT    8192
#define KS    7
#define TPAD  (TT + 6)
#define WN    (CH * CH * KS)   // 1835008

// conv tiling
#define MT 256            // t rows per CTA
#define NT 128            // o cols per CTA
#define BK 64             // channels per stage
#define NSTG 56           // 8 ci-chunks * 7 taps
#define LD 80             // smem row stride (bytes), conflict-free for ldmatrix
#define A_ROWS 264        // 262 used (256 + 6 halo)
#define ABYTES (A_ROWS * LD)   // 21120
#define BBYTES (NT * LD)       // 10240
#define SMEM_CONV (2 * ABYTES + 2 * BBYTES)  // 62720

// ---------------- device scratch (no runtime allocation) ----------------
__device__ __align__(16) int8_t g_xT[(size_t)BATCH * TPAD * CH]; // [b][t+3][c]
__device__ __align__(16) int8_t g_wq[(size_t)KS * CH * CH];      // [tap][o][i]
__device__ float        g_rms[BATCH * TT];
__device__ unsigned int g_max_bits;
__device__ double       g_wsum;
__device__ float        g_qmul;   // 127 / act_scale
__device__ float        g_winv;   // 1 / w_scale
__device__ float        g_comb;   // act_scale/127 * w_scale

// ---------------- ptx helpers (sm_80-level only; target is sm_103 non-'a') ---
__device__ __forceinline__ uint32_t smem_u32(const void* p) {
    uint32_t a;
    asm("{ .reg .u64 t; cvta.to.shared.u64 t, %1; cvt.u32.u64 %0, t; }"
        : "=r"(a) : "l"(p));
    return a;
}
#define CP_ASYNC16(dst, src) \
    asm volatile("cp.async.cg.shared.global [%0], [%1], 16;" \
                 :: "r"(dst), "l"(src) : "memory")
#define CP_COMMIT() asm volatile("cp.async.commit_group;" ::: "memory")
#define CP_WAIT1()  asm volatile("cp.async.wait_group 1;" ::: "memory")
#define CP_WAIT0()  asm volatile("cp.async.wait_group 0;" ::: "memory")

__device__ __forceinline__ void ldsm_x4(uint32_t* r, uint32_t addr) {
    asm volatile(
        "ldmatrix.sync.aligned.m8n8.x4.shared.b16 {%0,%1,%2,%3}, [%4];"
        : "=r"(r[0]), "=r"(r[1]), "=r"(r[2]), "=r"(r[3]) : "r"(addr));
}
__device__ __forceinline__ void mma_s8(int* c, const uint32_t* a,
                                       uint32_t b0, uint32_t b1) {
    asm volatile(
        "mma.sync.aligned.m16n8k32.row.col.s32.s8.s8.s32 "
        "{%0,%1,%2,%3}, {%4,%5,%6,%7}, {%8,%9}, {%0,%1,%2,%3};"
        : "+r"(c[0]), "+r"(c[1]), "+r"(c[2]), "+r"(c[3])
        : "r"(a[0]), "r"(a[1]), "r"(a[2]), "r"(a[3]), "r"(b0), "r"(b1));
}

// ---------------- K0: reset scalars + zero halo rows of g_xT ----------------
__global__ void k_init() {
    int idx = blockIdx.x * blockDim.x + threadIdx.x;
    if (idx == 0) { g_max_bits = 0u; g_wsum = 0.0; }
    int total = BATCH * 6 * CH;
    if (idx < total) {
        int b = idx / (6 * CH);
        int r = (idx / CH) % 6;
        int c = idx % CH;
        int row = (r < 3) ? r : (TT + r);
        g_xT[((size_t)b * TPAD + row) * CH + c] = 0;
    }
}

// ---------------- K1: sum |w| ----------------
__global__ void k_wsum(const float* __restrict__ w, int n) {
    double s = 0.0;
    for (int i = blockIdx.x * blockDim.x + threadIdx.x; i < n;
         i += gridDim.x * blockDim.x)
        s += (double)fabsf(w[i]);
#pragma unroll
    for (int o = 16; o; o >>= 1) s += __shfl_xor_sync(0xffffffffu, s, o);
    if ((threadIdx.x & 31) == 0) atomicAdd(&g_wsum, s);
}

// ---------------- K2: per-(b,t) rms + global max|normalized| ----------------
__global__ void k_stats(const float* __restrict__ x, const float* __restrict__ gamma) {
    int b  = blockIdx.y;
    int t0 = blockIdx.x * 32;
    int tt = threadIdx.x & 31;
    int cg = threadIdx.x >> 5;

    const float* xp = x + (size_t)b * CH * TT + t0 + tt;
    float ss = 0.f, mx = 0.f;
    for (int c = cg; c < CH; c += 8) {
        float v = xp[(size_t)c * TT];
        ss += v * v;
        mx = fmaxf(mx, fabsf(v * gamma[c]));
    }
    __shared__ float sss[8][33];
    __shared__ float smx[8][33];
    sss[cg][tt] = ss;
    smx[cg][tt] = mx;
    __syncthreads();
    if (cg == 0) {
        float S = 0.f, M = 0.f;
#pragma unroll
        for (int g = 0; g < 8; g++) { S += sss[g][tt]; M = fmaxf(M, smx[g][tt]); }
        float rms = 1.0f / sqrtf(S * (1.0f / (float)CH) + 1e-6f);
        g_rms[b * TT + t0 + tt] = rms;
        float cand = M * rms;
#pragma unroll
        for (int o = 16; o; o >>= 1)
            cand = fmaxf(cand, __shfl_xor_sync(0xffffffffu, cand, o));
        if (tt == 0) atomicMax(&g_max_bits, __float_as_uint(cand));
    }
}

// ---------------- K3: combine scalars ----------------
__global__ void k_combine() {
    float ma  = __uint_as_float(g_max_bits);
    float act = fmaxf(ma, 1e-5f);
    float ws  = fmaxf((float)(g_wsum / (double)WN), 1e-4f);
    g_qmul = 127.0f / act;
    g_winv = 1.0f / ws;
    g_comb = act * (1.0f / 127.0f) * ws;
}

// ---------------- K4: ternary weight quant -> g_wq[tap][o][i] ----------------
__global__ void k_wq(const float* __restrict__ w) {
    int idx = blockIdx.x * blockDim.x + threadIdx.x;
    if (idx >= WN) return;
    float winv = g_winv;
    float q = rintf(fminf(fmaxf(w[idx] * winv, -1.0f), 1.0f));
    int tap = idx % KS;
    int i   = (idx / KS) & (CH - 1);
    int o   = idx / (KS * CH);
    g_wq[(size_t)tap * (CH * CH) + (size_t)o * CH + i] = (int8_t)q;
}

// ---------------- K5: rmsnorm + quant + transpose -> g_xT ----------------
__global__ void k_quant(const float* __restrict__ x, const float* __restrict__ gamma) {
    __shared__ int8_t s[64][68];
    int b  = blockIdx.z;
    int t0 = blockIdx.x * 64;
    int c0 = blockIdx.y * 64;
    int tt = threadIdx.x & 63;
    int cg = threadIdx.x >> 6;
    float qm = g_qmul;
    float rr = g_rms[b * TT + t0 + tt];
    const float* xb = x + (size_t)b * CH * TT + t0 + tt;
#pragma unroll
    for (int cc = cg; cc < 64; cc += 4) {
        int c = c0 + cc;
        float v = xb[(size_t)c * TT];
        float n = v * rr * gamma[c];
        float q = rintf(fminf(fmaxf(n * qm, -128.0f), 127.0f));
        s[cc][tt] = (int8_t)q;
    }
    __syncthreads();
    int co = threadIdx.x & 63;
    int tg = threadIdx.x >> 6;
#pragma unroll
    for (int tw = tg; tw < 64; tw += 4) {
        g_xT[((size_t)b * TPAD + t0 + tw + 3) * CH + c0 + co] = s[co][tw];
    }
}

// ---------------- K6: pipelined IMMA conv-GEMM ----------------
// C[t, o] = sum_tap sum_c xT[t+tap, c] * wq[tap, o, c]
// Warp tile 64t x 64o. A/B double-buffered via cp.async.
struct ConvPtrs {
    const int8_t* xb;     // g_xT + (b*TPAD + t0)*CH
    const int8_t* wb;     // g_wq + o0*CH
    uint32_t As_u[2];
    uint32_t Bs_u[2];
};

__device__ __forceinline__ void issue_stage(int it, const ConvPtrs& P, int tid) {
    int tap = it % 7;
    int ci  = (it / 7) * BK;
    // B tile: 128 rows x 64B
    {
        uint32_t bd = P.Bs_u[it & 1];
        const int8_t* src = P.wb + (size_t)tap * (CH * CH) + ci;
#pragma unroll
        for (int v = 0; v < 2; v++) {
            int chunk = tid + v * 256;
            int row = chunk >> 2, seg = chunk & 3;
            CP_ASYNC16(bd + row * LD + seg * 16,
                       src + (size_t)row * CH + seg * 16);
        }
    }
    // A halo tile (new ci chunk): 262 rows x 64B
    if (tap == 0) {
        uint32_t ad = P.As_u[(it / 7) & 1];
        const int8_t* src = P.xb + ci;
        for (int chunk = tid; chunk < 262 * 4; chunk += 256) {
            int row = chunk >> 2, seg = chunk & 3;
            CP_ASYNC16(ad + row * LD + seg * 16,
                       src + (size_t)row * CH + seg * 16);
        }
    }
}

__global__ void __launch_bounds__(256, 1) k_conv(float* __restrict__ out) {
    extern __shared__ __align__(128) char sm[];

    int b  = blockIdx.z;
    int t0 = blockIdx.x * MT;
    int o0 = blockIdx.y * NT;
    int tid   = threadIdx.x;
    int warp  = tid >> 5;
    int lane  = tid & 31;
    int warpM = warp >> 1;   // 0..3 : 64 t rows
    int warpN = warp & 1;    // 0..1 : 64 o cols

    ConvPtrs P;
    P.xb = g_xT + ((size_t)b * TPAD + t0) * CH;
    P.wb = g_wq + (size_t)o0 * CH;
    uint32_t base = smem_u32(sm);
    P.As_u[0] = base;
    P.As_u[1] = base + ABYTES;
    P.Bs_u[0] = base + 2 * ABYTES;
    P.Bs_u[1] = base + 2 * ABYTES + BBYTES;

    int acc[4][8][4];
#pragma unroll
    for (int i = 0; i < 4; i++)
#pragma unroll
        for (int j = 0; j < 8; j++)
#pragma unroll
            for (int q = 0; q < 4; q++) acc[i][j][q] = 0;

    // ldmatrix lane addressing (tile = lane>>3):
    //  rowadd = ((lane>>3)&1)*8 + (lane&7), coladd = ((lane>>4)&1)*16
    uint32_t l_row = (((lane >> 3) & 1) << 3) + (lane & 7);
    uint32_t l_col = ((lane >> 4) & 1) << 4;

    issue_stage(0, P, tid);
    CP_COMMIT();

#pragma unroll 1
    for (int it = 0; it < NSTG; it++) {
        if (it < NSTG - 1) {
            issue_stage(it + 1, P, tid);
            CP_COMMIT();
            CP_WAIT1();
        } else {
            CP_WAIT0();
        }
        __syncthreads();

        int tap = it % 7;
        uint32_t a_base = P.As_u[(it / 7) & 1]
                        + (warpM * 64 + tap + l_row) * LD + l_col;
        uint32_t b_base = P.Bs_u[it & 1]
                        + (warpN * 64 + l_row) * LD + l_col;

#pragma unroll
        for (int kk = 0; kk < 2; kk++) {
            uint32_t br[16];
#pragma unroll
            for (int bn = 0; bn < 4; bn++)
                ldsm_x4(br + bn * 4, b_base + bn * 16 * LD + kk * 32);
#pragma unroll
            for (int mi = 0; mi < 4; mi++) {
                uint32_t ar[4];
                ldsm_x4(ar, a_base + mi * 16 * LD + kk * 32);
#pragma unroll
                for (int ni = 0; ni < 8; ni++) {
                    uint32_t b0 = br[(ni >> 1) * 4 + (ni & 1)];
                    uint32_t b1 = br[(ni >> 1) * 4 + (ni & 1) + 2];
                    mma_s8(acc[mi][ni], ar, b0, b1);
                }
            }
        }
        __syncthreads();
    }

    // ---- epilogue: per-warp 16x68 float staging, transpose to out[o][t] ----
    __syncthreads();
    float comb = g_comb;
    float* ep = reinterpret_cast<float*>(sm) + warp * (16 * 68);
    int r  = lane >> 2;
    int c2 = (lane & 3) * 2;
#pragma unroll 1
    for (int mi = 0; mi < 4; mi++) {
#pragma unroll
        for (int ni = 0; ni < 8; ni++) {
            ep[r * 68 + ni * 8 + c2]           = (float)acc[mi][ni][0] * comb;
            ep[r * 68 + ni * 8 + c2 + 1]       = (float)acc[mi][ni][1] * comb;
            ep[(r + 8) * 68 + ni * 8 + c2]     = (float)acc[mi][ni][2] * comb;
            ep[(r + 8) * 68 + ni * 8 + c2 + 1] = (float)acc[mi][ni][3] * comb;
        }
        __syncwarp();
        int tb = t0 + warpM * 64 + mi * 16;
#pragma unroll
        for (int rep = 0; rep < 2; rep++) {
            int ol = lane + rep * 32;
            float* op = out + ((size_t)b * CH + o0 + warpN * 64 + ol) * (size_t)TT + tb;
#pragma unroll
            for (int q = 0; q < 4; q++) {
                float4 v;
                v.x = ep[(q * 4 + 0) * 68 + ol];
                v.y = ep[(q * 4 + 1) * 68 + ol];
                v.z = ep[(q * 4 + 2) * 68 + ol];
                v.w = ep[(q * 4 + 3) * 68 + ol];
                reinterpret_cast<float4*>(op)[q] = v;
            }
        }
        __syncwarp();
    }
}

// ---------------- launch ----------------
extern "C" void kernel_launch(void* const* d_in, const int* in_sizes, int n_in,
                              void* d_out, int out_size) {
    const float* x     = (const float*)d_in[0];   // (8, 512, 8192)
    const float* w     = (const float*)d_in[1];   // (512, 512, 7)
    const float* gamma = (const float*)d_in[2];   // (512,)
    float* out = (float*)d_out;                   // (8, 512, 8192)

    cudaFuncSetAttribute(k_conv, cudaFuncAttributeMaxDynamicSharedMemorySize,
                         SMEM_CONV);

    k_init<<<96, 256>>>();
    k_wsum<<<448, 256>>>(w, WN);
    k_stats<<<dim3(TT / 32, BATCH), 256>>>(x, gamma);
    k_combine<<<1, 1>>>();
    k_wq<<<(WN + 255) / 256, 256>>>(w);
    k_quant<<<dim3(TT / 64, CH / 64, BATCH), 256>>>(x, gamma);
    k_conv<<<dim3(TT / MT, CH / NT, BATCH), 256, SMEM_CONV>>>(out);
}

// round 6
// speedup vs baseline: 2.8227x; 1.1562x over previous
#include <cuda_runtime.h>
#include <cstdint>

#define BATCH 8
#define CH    512
#define TT    8192
#define KS    7
#define TPAD  (TT + 6)
#define WN    (CH * CH * KS)   // 1835008

// conv tiling
#define MT 256            // t rows per CTA
#define NT 128            // o cols per CTA
#define BK 64             // channels per stage
#define NSTG 56           // 8 ci-chunks * 7 taps
#define LD 80             // smem row stride (bytes), conflict-free for ldmatrix
#define A_ROWS 264        // 262 used (256 + 6 halo)
#define ABYTES (A_ROWS * LD)   // 21120
#define BBYTES (NT * LD)       // 10240
#define NBUF 5                 // B ring slots
#define SMEM_CONV (2 * ABYTES + NBUF * BBYTES)  // 93440

// ---------------- device scratch (no runtime allocation) ----------------
__device__ __align__(16) int8_t g_xT[(size_t)BATCH * TPAD * CH]; // [b][t+3][c]
__device__ __align__(16) int8_t g_wq[(size_t)KS * CH * CH];      // [tap][o][i]
__device__ float        g_rms[BATCH * TT];
__device__ unsigned int g_max_bits;
__device__ double       g_wsum;
__device__ float        g_qmul;   // 127 / act_scale
__device__ float        g_winv;   // 1 / w_scale
__device__ float        g_comb;   // act_scale/127 * w_scale

// ---------------- ptx helpers (sm_80-level; harness target is sm_103) -------
__device__ __forceinline__ uint32_t smem_u32(const void* p) {
    uint32_t a;
    asm("{ .reg .u64 t; cvta.to.shared.u64 t, %1; cvt.u32.u64 %0, t; }"
        : "=r"(a) : "l"(p));
    return a;
}
#define CP_ASYNC16(dst, src) \
    asm volatile("cp.async.cg.shared.global [%0], [%1], 16;" \
                 :: "r"(dst), "l"(src) : "memory")
#define CP_COMMIT() asm volatile("cp.async.commit_group;" ::: "memory")
#define CP_WAIT3()  asm volatile("cp.async.wait_group 3;" ::: "memory")

__device__ __forceinline__ void ldsm_x4(uint32_t* r, uint32_t addr) {
    asm volatile(
        "ldmatrix.sync.aligned.m8n8.x4.shared.b16 {%0,%1,%2,%3}, [%4];"
        : "=r"(r[0]), "=r"(r[1]), "=r"(r[2]), "=r"(r[3]) : "r"(addr));
}
__device__ __forceinline__ void mma_s8(int* c, const uint32_t* a,
                                       uint32_t b0, uint32_t b1) {
    asm volatile(
        "mma.sync.aligned.m16n8k32.row.col.s32.s8.s8.s32 "
        "{%0,%1,%2,%3}, {%4,%5,%6,%7}, {%8,%9}, {%0,%1,%2,%3};"
        : "+r"(c[0]), "+r"(c[1]), "+r"(c[2]), "+r"(c[3])
        : "r"(a[0]), "r"(a[1]), "r"(a[2]), "r"(a[3]), "r"(b0), "r"(b1));
}

// ---------------- K0: reset scalars + zero halo rows of g_xT ----------------
__global__ void k_init() {
    int idx = blockIdx.x * blockDim.x + threadIdx.x;
    if (idx == 0) { g_max_bits = 0u; g_wsum = 0.0; }
    int total = BATCH * 6 * CH;
    if (idx < total) {
        int b = idx / (6 * CH);
        int r = (idx / CH) % 6;
        int c = idx % CH;
        int row = (r < 3) ? r : (TT + r);
        g_xT[((size_t)b * TPAD + row) * CH + c] = 0;
    }
}

// ---------------- K1: sum |w| ----------------
__global__ void k_wsum(const float* __restrict__ w, int n) {
    double s = 0.0;
    for (int i = blockIdx.x * blockDim.x + threadIdx.x; i < n;
         i += gridDim.x * blockDim.x)
        s += (double)fabsf(w[i]);
#pragma unroll
    for (int o = 16; o; o >>= 1) s += __shfl_xor_sync(0xffffffffu, s, o);
    if ((threadIdx.x & 31) == 0) atomicAdd(&g_wsum, s);
}

// ---------------- K2: per-(b,t) rms + global max|normalized| ----------------
__global__ void k_stats(const float* __restrict__ x, const float* __restrict__ gamma) {
    int b  = blockIdx.y;
    int t0 = blockIdx.x * 32;
    int tt = threadIdx.x & 31;
    int cg = threadIdx.x >> 5;

    const float* xp = x + (size_t)b * CH * TT + t0 + tt;
    float ss = 0.f, mx = 0.f;
    for (int c = cg; c < CH; c += 8) {
        float v = xp[(size_t)c * TT];
        ss += v * v;
        mx = fmaxf(mx, fabsf(v * gamma[c]));
    }
    __shared__ float sss[8][33];
    __shared__ float smx[8][33];
    sss[cg][tt] = ss;
    smx[cg][tt] = mx;
    __syncthreads();
    if (cg == 0) {
        float S = 0.f, M = 0.f;
#pragma unroll
        for (int g = 0; g < 8; g++) { S += sss[g][tt]; M = fmaxf(M, smx[g][tt]); }
        float rms = 1.0f / sqrtf(S * (1.0f / (float)CH) + 1e-6f);
        g_rms[b * TT + t0 + tt] = rms;
        float cand = M * rms;
#pragma unroll
        for (int o = 16; o; o >>= 1)
            cand = fmaxf(cand, __shfl_xor_sync(0xffffffffu, cand, o));
        if (tt == 0) atomicMax(&g_max_bits, __float_as_uint(cand));
    }
}

// ---------------- K3: combine scalars ----------------
__global__ void k_combine() {
    float ma  = __uint_as_float(g_max_bits);
    float act = fmaxf(ma, 1e-5f);
    float ws  = fmaxf((float)(g_wsum / (double)WN), 1e-4f);
    g_qmul = 127.0f / act;
    g_winv = 1.0f / ws;
    g_comb = act * (1.0f / 127.0f) * ws;
}

// ---------------- K4: ternary weight quant -> g_wq[tap][o][i] ----------------
__global__ void k_wq(const float* __restrict__ w) {
    int idx = blockIdx.x * blockDim.x + threadIdx.x;
    if (idx >= WN) return;
    float winv = g_winv;
    float q = rintf(fminf(fmaxf(w[idx] * winv, -1.0f), 1.0f));
    int tap = idx % KS;
    int i   = (idx / KS) & (CH - 1);
    int o   = idx / (KS * CH);
    g_wq[(size_t)tap * (CH * CH) + (size_t)o * CH + i] = (int8_t)q;
}

// ---------------- K5: rmsnorm + quant + transpose -> g_xT ----------------
__global__ void k_quant(const float* __restrict__ x, const float* __restrict__ gamma) {
    __shared__ int8_t s[64][68];
    int b  = blockIdx.z;
    int t0 = blockIdx.x * 64;
    int c0 = blockIdx.y * 64;
    int tt = threadIdx.x & 63;
    int cg = threadIdx.x >> 6;
    float qm = g_qmul;
    float rr = g_rms[b * TT + t0 + tt];
    const float* xb = x + (size_t)b * CH * TT + t0 + tt;
#pragma unroll
    for (int cc = cg; cc < 64; cc += 4) {
        int c = c0 + cc;
        float v = xb[(size_t)c * TT];
        float n = v * rr * gamma[c];
        float q = rintf(fminf(fmaxf(n * qm, -128.0f), 127.0f));
        s[cc][tt] = (int8_t)q;
    }
    __syncthreads();
    int co = threadIdx.x & 63;
    int tg = threadIdx.x >> 6;
#pragma unroll
    for (int tw = tg; tw < 64; tw += 4) {
        g_xT[((size_t)b * TPAD + t0 + tw + 3) * CH + c0 + co] = s[co][tw];
    }
}

// ---------------- K6: deep-pipelined IMMA conv-GEMM ----------------
// C[t, o] = sum_tap sum_c xT[t+tap, c] * wq[tap, o, c]
// 512 threads, warp tile 64t x 32o. B: 5-slot ring, lookahead 3. A: 2 buffers.
struct ConvPtrs {
    const int8_t* xb;     // g_xT + (b*TPAD + t0)*CH
    const int8_t* wb;     // g_wq + o0*CH
    uint32_t As_u[2];
    uint32_t Bs_u[NBUF];
};

__device__ __forceinline__ void issue_stage(int j, const ConvPtrs& P, int tid) {
    int tap = j % 7;
    int ci  = (j / 7) * BK;
    // B tile: 128 rows x 64B = 512 x 16B chunks, exactly one per thread
    {
        uint32_t bd = P.Bs_u[j % NBUF];
        const int8_t* src = P.wb + (size_t)tap * (CH * CH) + ci;
        int row = tid >> 2, seg = tid & 3;
        CP_ASYNC16(bd + row * LD + seg * 16,
                   src + (size_t)row * CH + seg * 16);
    }
    // A halo tile (new ci chunk): 262 rows x 64B
    if (tap == 0) {
        uint32_t ad = P.As_u[(j / 7) & 1];
        const int8_t* src = P.xb + ci;
        for (int chunk = tid; chunk < 262 * 4; chunk += 512) {
            int row = chunk >> 2, seg = chunk & 3;
            CP_ASYNC16(ad + row * LD + seg * 16,
                       src + (size_t)row * CH + seg * 16);
        }
    }
}

__global__ void __launch_bounds__(512, 1) k_conv(float* __restrict__ out) {
    extern __shared__ __align__(128) char sm[];

    int b  = blockIdx.z;
    int t0 = blockIdx.x * MT;
    int o0 = blockIdx.y * NT;
    int tid   = threadIdx.x;
    int warp  = tid >> 5;
    int lane  = tid & 31;
    int warpM = warp >> 2;   // 0..3 : 64 t rows
    int warpN = warp & 3;    // 0..3 : 32 o cols

    ConvPtrs P;
    P.xb = g_xT + ((size_t)b * TPAD + t0) * CH;
    P.wb = g_wq + (size_t)o0 * CH;
    uint32_t base = smem_u32(sm);
    P.As_u[0] = base;
    P.As_u[1] = base + ABYTES;
#pragma unroll
    for (int s = 0; s < NBUF; s++) P.Bs_u[s] = base + 2 * ABYTES + s * BBYTES;

    int acc[4][4][4];
#pragma unroll
    for (int i = 0; i < 4; i++)
#pragma unroll
        for (int j = 0; j < 4; j++)
#pragma unroll
            for (int q = 0; q < 4; q++) acc[i][j][q] = 0;

    // ldmatrix lane addressing for x4 (covers 16 rows x 32B):
    uint32_t l_row = (((lane >> 3) & 1) << 3) + (lane & 7);
    uint32_t l_col = ((lane >> 4) & 1) << 4;

    // prologue: stages 0..2 in flight
    issue_stage(0, P, tid); CP_COMMIT();
    issue_stage(1, P, tid); CP_COMMIT();
    issue_stage(2, P, tid); CP_COMMIT();

#pragma unroll 1
    for (int it = 0; it < NSTG; it++) {
        // safe: slot (it+3)%5 == (it-2)%5; all warps passed iter it-1's barrier,
        // so stage it-2 compute (and older) is complete CTA-wide.
        if (it + 3 < NSTG) issue_stage(it + 3, P, tid);
        CP_COMMIT();
        CP_WAIT3();          // stage it data complete
        __syncthreads();     // visibility + slot-reuse fence

        int tap = it % 7;
        uint32_t a_base = P.As_u[(it / 7) & 1]
                        + (warpM * 64 + tap + l_row) * LD + l_col;
        uint32_t b_base = P.Bs_u[it % NBUF]
                        + (warpN * 32 + l_row) * LD + l_col;

#pragma unroll
        for (int kk = 0; kk < 2; kk++) {
            uint32_t br[8];
#pragma unroll
            for (int bn = 0; bn < 2; bn++)
                ldsm_x4(br + bn * 4, b_base + bn * 16 * LD + kk * 32);
#pragma unroll
            for (int mi = 0; mi < 4; mi++) {
                uint32_t ar[4];
                ldsm_x4(ar, a_base + mi * 16 * LD + kk * 32);
#pragma unroll
                for (int ni = 0; ni < 4; ni++) {
                    uint32_t b0 = br[(ni >> 1) * 4 + (ni & 1)];
                    uint32_t b1 = br[(ni >> 1) * 4 + (ni & 1) + 2];
                    mma_s8(acc[mi][ni], ar, b0, b1);
                }
            }
        }
    }

    // ---- epilogue: per-warp 16x36 float staging, transpose to out[o][t] ----
    __syncthreads();
    float comb = g_comb;
    float* ep = reinterpret_cast<float*>(sm) + warp * (16 * 36);
    int r  = lane >> 2;
    int c2 = (lane & 3) * 2;
#pragma unroll 1
    for (int mi = 0; mi < 4; mi++) {
#pragma unroll
        for (int ni = 0; ni < 4; ni++) {
            ep[r * 36 + ni * 8 + c2]           = (float)acc[mi][ni][0] * comb;
            ep[r * 36 + ni * 8 + c2 + 1]       = (float)acc[mi][ni][1] * comb;
            ep[(r + 8) * 36 + ni * 8 + c2]     = (float)acc[mi][ni][2] * comb;
            ep[(r + 8) * 36 + ni * 8 + c2 + 1] = (float)acc[mi][ni][3] * comb;
        }
        __syncwarp();
        int tb = t0 + warpM * 64 + mi * 16;
        int ol = lane;   // 32 o values per warp
        float* op = out + ((size_t)b * CH + o0 + warpN * 32 + ol) * (size_t)TT + tb;
#pragma unroll
        for (int q = 0; q < 4; q++) {
            float4 v;
            v.x = ep[(q * 4 + 0) * 36 + ol];
            v.y = ep[(q * 4 + 1) * 36 + ol];
            v.z = ep[(q * 4 + 2) * 36 + ol];
            v.w = ep[(q * 4 + 3) * 36 + ol];
            reinterpret_cast<float4*>(op)[q] = v;
        }
        __syncwarp();
    }
}

// ---------------- launch ----------------
extern "C" void kernel_launch(void* const* d_in, const int* in_sizes, int n_in,
                              void* d_out, int out_size) {
    const float* x     = (const float*)d_in[0];   // (8, 512, 8192)
    const float* w     = (const float*)d_in[1];   // (512, 512, 7)
    const float* gamma = (const float*)d_in[2];   // (512,)
    float* out = (float*)d_out;                   // (8, 512, 8192)

    cudaFuncSetAttribute(k_conv, cudaFuncAttributeMaxDynamicSharedMemorySize,
                         SMEM_CONV);

    k_init<<<96, 256>>>();
    k_wsum<<<448, 256>>>(w, WN);
    k_stats<<<dim3(TT / 32, BATCH), 256>>>(x, gamma);
    k_combine<<<1, 1>>>();
    k_wq<<<(WN + 255) / 256, 256>>>(w);
    k_quant<<<dim3(TT / 64, CH / 64, BATCH), 256>>>(x, gamma);
    k_conv<<<dim3(TT / MT, CH / NT, BATCH), 512, SMEM_CONV>>>(out);
}

// round 7
// speedup vs baseline: 2.8520x; 1.0104x over previous
#include <cuda_runtime.h>
#include <cstdint>

#define BATCH 8
#define CH    512
#define TT    8192
#define KS    7
#define TPAD  (TT + 6)
#define WN    (CH * CH * KS)   // 1835008

// conv tiling
#define MT 256            // t rows per CTA
#define NT 128            // o cols per CTA
#define BK 128            // channels per stage
#define NSTG 28           // 4 ci-chunks * 7 taps
#define LD 144            // smem row stride: 16B-aligned, ldmatrix conflict-free
#define A_ROWS 264        // 262 used (256 + 6 halo)
#define ABYTES (A_ROWS * LD)   // 38016
#define BBYTES (NT * LD)       // 18432
#define NBUF 4                 // B ring slots
#define SMEM_CONV (2 * ABYTES + NBUF * BBYTES)  // 149760

#define NSTATS 2048       // stats blocks (256 t-tiles * 8 batch)
#define NWSUM  448        // wsum partial blocks

// ---------------- device scratch (no runtime allocation) ----------------
__device__ __align__(16) int8_t g_xT[(size_t)BATCH * TPAD * CH]; // [b][t+3][c]
__device__ __align__(16) int8_t g_wq[(size_t)KS * CH * CH];      // [tap][o][i]
__device__ float        g_rms[BATCH * TT];
__device__ float        g_pmax[NSTATS];
__device__ double       g_psum[NWSUM];
__device__ float        g_qmul;   // 127 / act_scale
__device__ float        g_winv;   // 1 / w_scale
__device__ float        g_comb;   // act_scale/127 * w_scale

// ---------------- ptx helpers (sm_80-level; harness target is sm_103) -------
__device__ __forceinline__ uint32_t smem_u32(const void* p) {
    uint32_t a;
    asm("{ .reg .u64 t; cvta.to.shared.u64 t, %1; cvt.u32.u64 %0, t; }"
        : "=r"(a) : "l"(p));
    return a;
}
#define CP_ASYNC16(dst, src) \
    asm volatile("cp.async.cg.shared.global [%0], [%1], 16;" \
                 :: "r"(dst), "l"(src) : "memory")
#define CP_COMMIT() asm volatile("cp.async.commit_group;" ::: "memory")
#define CP_WAIT2()  asm volatile("cp.async.wait_group 2;" ::: "memory")

__device__ __forceinline__ void ldsm_x4(uint32_t* r, uint32_t addr) {
    asm volatile(
        "ldmatrix.sync.aligned.m8n8.x4.shared.b16 {%0,%1,%2,%3}, [%4];"
        : "=r"(r[0]), "=r"(r[1]), "=r"(r[2]), "=r"(r[3]) : "r"(addr));
}
__device__ __forceinline__ void mma_s8(int* c, const uint32_t* a,
                                       uint32_t b0, uint32_t b1) {
    asm volatile(
        "mma.sync.aligned.m16n8k32.row.col.s32.s8.s8.s32 "
        "{%0,%1,%2,%3}, {%4,%5,%6,%7}, {%8,%9}, {%0,%1,%2,%3};"
        : "+r"(c[0]), "+r"(c[1]), "+r"(c[2]), "+r"(c[3])
        : "r"(a[0]), "r"(a[1]), "r"(a[2]), "r"(a[3]), "r"(b0), "r"(b1));
}

// ---------------- L1: k_pre — stats + wsum partials + halo zero -------------
// blocks [0,2048): per-(b, 32t) rms + block max|normalized|  -> g_rms, g_pmax
// blocks [2048,2496): |w| partial sums                       -> g_psum
// blocks [2496,2592): zero the 6 halo rows of g_xT
__global__ void k_pre(const float* __restrict__ x,
                      const float* __restrict__ gamma,
                      const float* __restrict__ w) {
    int bid = blockIdx.x;
    int tid = threadIdx.x;
    if (bid < NSTATS) {
        int b  = bid >> 8;
        int t0 = (bid & 255) << 5;
        int tt = tid & 31;
        int cg = tid >> 5;
        const float* xp = x + (size_t)b * CH * TT + t0 + tt;
        float ss = 0.f, mx = 0.f;
        for (int c = cg; c < CH; c += 8) {
            float v = xp[(size_t)c * TT];
            ss += v * v;
            mx = fmaxf(mx, fabsf(v * gamma[c]));
        }
        __shared__ float sss[8][33];
        __shared__ float smx[8][33];
        sss[cg][tt] = ss;
        smx[cg][tt] = mx;
        __syncthreads();
        if (cg == 0) {
            float S = 0.f, M = 0.f;
#pragma unroll
            for (int g = 0; g < 8; g++) { S += sss[g][tt]; M = fmaxf(M, smx[g][tt]); }
            float rms = 1.0f / sqrtf(S * (1.0f / (float)CH) + 1e-6f);
            g_rms[b * TT + t0 + tt] = rms;
            float cand = M * rms;
#pragma unroll
            for (int o = 16; o; o >>= 1)
                cand = fmaxf(cand, __shfl_xor_sync(0xffffffffu, cand, o));
            if (tt == 0) g_pmax[bid] = cand;
        }
    } else if (bid < NSTATS + NWSUM) {
        int j = bid - NSTATS;
        double s = 0.0;
        for (int i = j * 256 + tid; i < WN; i += NWSUM * 256)
            s += (double)fabsf(w[i]);
#pragma unroll
        for (int o = 16; o; o >>= 1) s += __shfl_xor_sync(0xffffffffu, s, o);
        __shared__ double sd[8];
        if ((tid & 31) == 0) sd[tid >> 5] = s;
        __syncthreads();
        if (tid == 0) {
            double t = 0.0;
#pragma unroll
            for (int g = 0; g < 8; g++) t += sd[g];
            g_psum[j] = t;
        }
    } else {
        int idx = (bid - NSTATS - NWSUM) * 256 + tid;   // [0, 24576)
        int b = idx / (6 * CH);
        int r = (idx / CH) % 6;
        int c = idx % CH;
        int row = (r < 3) ? r : (TT + r);
        g_xT[((size_t)b * TPAD + row) * CH + c] = 0;
    }
}

// ---------------- L2: combine partials -> scalars ----------------
__global__ void k_combine() {
    int tid = threadIdx.x;
    __shared__ double sd[256];
    __shared__ float  sf[256];
    double s = 0.0;
    for (int i = tid; i < NWSUM; i += 256) s += g_psum[i];
    float m = 0.f;
    for (int i = tid; i < NSTATS; i += 256) m = fmaxf(m, g_pmax[i]);
    sd[tid] = s;
    sf[tid] = m;
    __syncthreads();
    for (int o = 128; o; o >>= 1) {
        if (tid < o) {
            sd[tid] += sd[tid + o];
            sf[tid] = fmaxf(sf[tid], sf[tid + o]);
        }
        __syncthreads();
    }
    if (tid == 0) {
        float act = fmaxf(sf[0], 1e-5f);
        float ws  = fmaxf((float)(sd[0] / (double)WN), 1e-4f);
        g_qmul = 127.0f / act;
        g_winv = 1.0f / ws;
        g_comb = act * (1.0f / 127.0f) * ws;
    }
}

// ---------------- L3: k_mid — weight quant + act quant/transpose ------------
// blocks [0,8192): quant tile (decode old dim3(128, 8, 8))
// blocks [8192,15360): ternary weight quant
__global__ void k_mid(const float* __restrict__ x,
                      const float* __restrict__ gamma,
                      const float* __restrict__ w) {
    int bid = blockIdx.x;
    int tid = threadIdx.x;
    if (bid < 8192) {
        __shared__ int8_t s[64][68];
        int bx = bid & 127;
        int by = (bid >> 7) & 7;
        int b  = bid >> 10;
        int t0 = bx * 64;
        int c0 = by * 64;
        int tt = tid & 63;
        int cg = tid >> 6;
        float qm = g_qmul;
        float rr = g_rms[b * TT + t0 + tt];
        const float* xb = x + (size_t)b * CH * TT + t0 + tt;
#pragma unroll
        for (int cc = cg; cc < 64; cc += 4) {
            int c = c0 + cc;
            float v = xb[(size_t)c * TT];
            float n = v * rr * gamma[c];
            float q = rintf(fminf(fmaxf(n * qm, -128.0f), 127.0f));
            s[cc][tt] = (int8_t)q;
        }
        __syncthreads();
        int co = tid & 63;
        int tg = tid >> 6;
#pragma unroll
        for (int tw = tg; tw < 64; tw += 4) {
            g_xT[((size_t)b * TPAD + t0 + tw + 3) * CH + c0 + co] = s[co][tw];
        }
    } else {
        int idx = (bid - 8192) * 256 + tid;
        if (idx < WN) {
            float winv = g_winv;
            float q = rintf(fminf(fmaxf(w[idx] * winv, -1.0f), 1.0f));
            int tap = idx % KS;
            int i   = (idx / KS) & (CH - 1);
            int o   = idx / (KS * CH);
            g_wq[(size_t)tap * (CH * CH) + (size_t)o * CH + i] = (int8_t)q;
        }
    }
}

// ---------------- L4: deep-pipelined IMMA conv-GEMM (BK=128) ----------------
// C[t, o] = sum_tap sum_c xT[t+tap, c] * wq[tap, o, c]
// 512 threads, warp tile 64t x 32o. B: 4-slot ring, lookahead 2. A: 2 buffers.
struct ConvPtrs {
    const int8_t* xb;
    const int8_t* wb;
    uint32_t As_u[2];
    uint32_t Bs_u[NBUF];
};

__device__ __forceinline__ void issue_stage(int j, const ConvPtrs& P, int tid) {
    int tap = j % 7;
    int ci  = (j / 7) * BK;
    // B tile: 128 rows x 128B = 1024 x 16B chunks -> 2 per thread
    {
        uint32_t bd = P.Bs_u[j & (NBUF - 1)];
        const int8_t* src = P.wb + (size_t)tap * (CH * CH) + ci;
#pragma unroll
        for (int v = 0; v < 2; v++) {
            int chunk = tid + v * 512;
            int row = chunk >> 3, seg = chunk & 7;
            CP_ASYNC16(bd + row * LD + seg * 16,
                       src + (size_t)row * CH + seg * 16);
        }
    }
    // A halo tile (new ci chunk): 262 rows x 128B
    if (tap == 0) {
        uint32_t ad = P.As_u[(j / 7) & 1];
        const int8_t* src = P.xb + ci;
        for (int chunk = tid; chunk < 262 * 8; chunk += 512) {
            int row = chunk >> 3, seg = chunk & 7;
            CP_ASYNC16(ad + row * LD + seg * 16,
                       src + (size_t)row * CH + seg * 16);
        }
    }
}

__global__ void __launch_bounds__(512, 1) k_conv(float* __restrict__ out) {
    extern __shared__ __align__(128) char sm[];

    int b  = blockIdx.z;
    int t0 = blockIdx.x * MT;
    int o0 = blockIdx.y * NT;
    int tid   = threadIdx.x;
    int warp  = tid >> 5;
    int lane  = tid & 31;
    int warpM = warp >> 2;   // 0..3 : 64 t rows
    int warpN = warp & 3;    // 0..3 : 32 o cols

    ConvPtrs P;
    P.xb = g_xT + ((size_t)b * TPAD + t0) * CH;
    P.wb = g_wq + (size_t)o0 * CH;
    uint32_t base = smem_u32(sm);
    P.As_u[0] = base;
    P.As_u[1] = base + ABYTES;
#pragma unroll
    for (int s = 0; s < NBUF; s++) P.Bs_u[s] = base + 2 * ABYTES + s * BBYTES;

    int acc[4][4][4];
#pragma unroll
    for (int i = 0; i < 4; i++)
#pragma unroll
        for (int j = 0; j < 4; j++)
#pragma unroll
            for (int q = 0; q < 4; q++) acc[i][j][q] = 0;

    uint32_t l_row = (((lane >> 3) & 1) << 3) + (lane & 7);
    uint32_t l_col = ((lane >> 4) & 1) << 4;

    issue_stage(0, P, tid); CP_COMMIT();
    issue_stage(1, P, tid); CP_COMMIT();

#pragma unroll 1
    for (int it = 0; it < NSTG; it++) {
        // slot (it+2)%4 == (it-2)%4: all warps are past barrier(it-1), so the
        // newest stage any warp may still be computing is it-1 -> distinct slot.
        if (it + 2 < NSTG) issue_stage(it + 2, P, tid);
        CP_COMMIT();
        CP_WAIT2();          // stage it data complete
        __syncthreads();     // visibility + slot-reuse fence

        int tap = it % 7;
        uint32_t a_base = P.As_u[(it / 7) & 1]
                        + (warpM * 64 + tap + l_row) * LD + l_col;
        uint32_t b_base = P.Bs_u[it & (NBUF - 1)]
                        + (warpN * 32 + l_row) * LD + l_col;

#pragma unroll
        for (int kk = 0; kk < 4; kk++) {
            uint32_t br[8];
#pragma unroll
            for (int bn = 0; bn < 2; bn++)
                ldsm_x4(br + bn * 4, b_base + bn * 16 * LD + kk * 32);
#pragma unroll
            for (int mi = 0; mi < 4; mi++) {
                uint32_t ar[4];
                ldsm_x4(ar, a_base + mi * 16 * LD + kk * 32);
#pragma unroll
                for (int ni = 0; ni < 4; ni++) {
                    uint32_t b0 = br[(ni >> 1) * 4 + (ni & 1)];
                    uint32_t b1 = br[(ni >> 1) * 4 + (ni & 1) + 2];
                    mma_s8(acc[mi][ni], ar, b0, b1);
                }
            }
        }
    }

    // ---- epilogue: per-warp 16x36 float staging, transpose to out[o][t] ----
    __syncthreads();
    float comb = g_comb;
    float* ep = reinterpret_cast<float*>(sm) + warp * (16 * 36);
    int r  = lane >> 2;
    int c2 = (lane & 3) * 2;
#pragma unroll 1
    for (int mi = 0; mi < 4; mi++) {
#pragma unroll
        for (int ni = 0; ni < 4; ni++) {
            ep[r * 36 + ni * 8 + c2]           = (float)acc[mi][ni][0] * comb;
            ep[r * 36 + ni * 8 + c2 + 1]       = (float)acc[mi][ni][1] * comb;
            ep[(r + 8) * 36 + ni * 8 + c2]     = (float)acc[mi][ni][2] * comb;
            ep[(r + 8) * 36 + ni * 8 + c2 + 1] = (float)acc[mi][ni][3] * comb;
        }
        __syncwarp();
        int tb = t0 + warpM * 64 + mi * 16;
        int ol = lane;
        float* op = out + ((size_t)b * CH + o0 + warpN * 32 + ol) * (size_t)TT + tb;
#pragma unroll
        for (int q = 0; q < 4; q++) {
            float4 v;
            v.x = ep[(q * 4 + 0) * 36 + ol];
            v.y = ep[(q * 4 + 1) * 36 + ol];
            v.z = ep[(q * 4 + 2) * 36 + ol];
            v.w = ep[(q * 4 + 3) * 36 + ol];
            reinterpret_cast<float4*>(op)[q] = v;
        }
        __syncwarp();
    }
}

// ---------------- launch (exactly 4: conv is the 4th = profiled slot) -------
extern "C" void kernel_launch(void* const* d_in, const int* in_sizes, int n_in,
                              void* d_out, int out_size) {
    const float* x     = (const float*)d_in[0];   // (8, 512, 8192)
    const float* w     = (const float*)d_in[1];   // (512, 512, 7)
    const float* gamma = (const float*)d_in[2];   // (512,)
    float* out = (float*)d_out;                   // (8, 512, 8192)

    cudaFuncSetAttribute(k_conv, cudaFuncAttributeMaxDynamicSharedMemorySize,
                         SMEM_CONV);

    k_pre<<<NSTATS + NWSUM + 96, 256>>>(x, gamma, w);
    k_combine<<<1, 256>>>();
    k_mid<<<8192 + 7168, 256>>>(x, gamma, w);
    k_conv<<<dim3(TT / MT, CH / NT, BATCH), 512, SMEM_CONV>>>(out);
}